// round 1
// baseline (speedup 1.0000x reference)
#include <cuda_runtime.h>
#include <math.h>
#include <math_constants.h>

#define H    256
#define H2   512
#define NMAP 131072
#define NSCH 131072
#define ATOT (NMAP + NSCH)
#define BR   64
#define NBLK_C (ATOT / BR)       // 4096
#define KT   16
#define XP   66                  // Xs row pad (conflict-free transposed stores)
#define HP   260                 // Hs row pad (mult of 4, spreads banks)

// ---------------- device scratch (allowed: __device__ globals) ----------------
static __device__ __align__(16) float g_keys[(size_t)ATOT * H];        // 268 MB
static __device__ __align__(16) float g_red[256 * H];
static __device__ __align__(16) float g_kq[4 * H];
static __device__ float g_cK[4];
static __device__ float g_pm[4 * NBLK_C];
static __device__ float g_ps[4 * NBLK_C];
static __device__ __align__(16) float g_pacc[(size_t)4 * NBLK_C * H];  // 16.8 MB
static __device__ float g_m2[4 * 64];
static __device__ float g_s2[4 * 64];
static __device__ __align__(16) float g_acc2[4 * 64 * H];
static __device__ __align__(16) float g_attn_out[H];
static __device__ unsigned int g_lmax;
static __device__ float g_lpart[256];

// ordered-int encoding for exact (order-independent) float atomicMax
__device__ __forceinline__ unsigned int fkey(float f) {
    unsigned int b = __float_as_uint(f);
    return (b & 0x80000000u) ? ~b : (b | 0x80000000u);
}
__device__ __forceinline__ float funkey(unsigned int k) {
    unsigned int b = (k & 0x80000000u) ? (k & 0x7fffffffu) : ~k;
    return __uint_as_float(b);
}

// ---------------- kernel A: column partial sums of all_embeddings ----------------
__global__ void kA(const float* __restrict__ all_emb) {
    const int c = threadIdx.x;          // 256 threads = 256 cols
    const int b = blockIdx.x;           // 256 blocks, 512 rows each
    const float* p = all_emb + (size_t)b * 512 * H + c;
    float s = 0.f;
#pragma unroll 8
    for (int r = 0; r < 512; r++) s += p[(size_t)r * H];
    g_red[b * H + c] = s;
}

// ---------------- kernel B: g-mean finish, query MLP, q proj, kq/cK fold ----------------
__global__ void kB(const float* __restrict__ qgW1, const float* __restrict__ qgb1,
                   const float* __restrict__ qgW2, const float* __restrict__ qgb2,
                   const float* __restrict__ Wq,  const float* __restrict__ bq,
                   const float* __restrict__ Wk,  const float* __restrict__ bk) {
    __shared__ float xs[H], h1[H], q2[H], qv[H];
    const int t = threadIdx.x;

    float s = 0.f;
#pragma unroll 8
    for (int b = 0; b < 256; b++) s += g_red[b * H + t];
    xs[t] = s * (1.0f / 131072.0f);
    __syncthreads();

    float a = qgb1[t];
#pragma unroll 8
    for (int c = 0; c < H; c++) a = fmaf(qgW1[(size_t)t * H + c], xs[c], a);
    h1[t] = fmaxf(a, 0.f);
    __syncthreads();

    a = qgb2[t];
#pragma unroll 8
    for (int c = 0; c < H; c++) a = fmaf(qgW2[(size_t)t * H + c], h1[c], a);
    q2[t] = a;
    __syncthreads();

    a = bq[t];
#pragma unroll 8
    for (int c = 0; c < H; c++) a = fmaf(Wq[(size_t)t * H + c], q2[c], a);
    qv[t] = a;
    __syncthreads();

    // kq_h[c] = sum_d Wk[h*64+d][c] * qv[h*64+d]   (coalesced: thread t = col c)
#pragma unroll
    for (int h = 0; h < 4; h++) {
        float a2 = 0.f;
#pragma unroll 8
        for (int d = 0; d < 64; d++)
            a2 = fmaf(Wk[(size_t)(h * 64 + d) * H + t], qv[h * 64 + d], a2);
        g_kq[h * H + t] = a2;
    }
    if (t < 4) {
        float a2 = 0.f;
        for (int d = 0; d < 64; d++) a2 = fmaf(bk[t * 64 + d], qv[t * 64 + d], a2);
        g_cK[t] = a2;
    }
}

// ---------------- kernel C: fused gather + MLP + keys + scores + softmax partials ----------------
__global__ void __launch_bounds__(256, 2)
kC(const float* __restrict__ qubit_emb, const float* __restrict__ qpu_emb,
   const float* __restrict__ gate_emb,  const float* __restrict__ time_tab,
   const float* __restrict__ mW1, const float* __restrict__ mb1,
   const float* __restrict__ mW2, const float* __restrict__ mb2,
   const float* __restrict__ sW1, const float* __restrict__ sb1,
   const float* __restrict__ sW2, const float* __restrict__ sb2,
   const int* __restrict__ map_qubit, const int* __restrict__ map_qpu,
   const int* __restrict__ sched_gate, const int* __restrict__ sched_time) {
    extern __shared__ float sm[];
    float* Ws  = sm;                       // KT*H   = 4096 floats
    float* Xs  = Ws  + KT * H;             // KT*XP  = 1056
    float* Hs  = Xs  + KT * XP;            // BR*HP  = 16640
    float* kqs = Hs  + BR * HP;            // 4*H    = 1024
    float* sc  = kqs + 4 * H;              // BR*4
    float* esh = sc  + BR * 4;             // BR*4
    float* mh  = esh + BR * 4;             // 4
    int*   idxA = (int*)(mh + 4);          // BR
    int*   idxB = idxA + BR;               // BR

    const int tid = threadIdx.x;
    const int blk = blockIdx.x;
    const long rowBase = (long)blk * BR;
    const bool isMap = (rowBase < NMAP);

    const float* T1 = isMap ? qubit_emb : gate_emb;
    const float* T2 = isMap ? qpu_emb   : time_tab;
    const float* W1 = isMap ? mW1 : sW1;
    const float* b1 = isMap ? mb1 : sb1;
    const float* W2 = isMap ? mW2 : sW2;
    const float* b2 = isMap ? mb2 : sb2;

    if (tid < BR) {
        long ib = isMap ? (rowBase + tid) : (rowBase - NMAP + tid);
        idxA[tid] = isMap ? map_qubit[ib] : sched_gate[ib];
        idxB[tid] = isMap ? map_qpu[ib]   : sched_time[ib];
    }
    for (int i = tid; i < 4 * H; i += 256) kqs[i] = g_kq[i];
    __syncthreads();

    const int warp = tid >> 5, lane = tid & 31;
    const int r0 = warp * 8;   // 8 warps x 8 rows = 64
    const int c0 = lane * 8;   // 32 lanes x 8 cols = 256

    float acc[8][8];
#pragma unroll
    for (int i = 0; i < 8; i++)
#pragma unroll
        for (int j = 0; j < 8; j++) acc[i][j] = 0.f;

    const int xr  = tid >> 2;
    const int xkv = (tid & 3) * 4;

    // ---- GEMM1: X[64x512] @ W1^T -> h[64x256] ----
    for (int kt = 0; kt < H2 / KT; kt++) {
        const int k0 = kt * KT;
        {   // X k-slice (gather), stored transposed Xs[k][r]
            const float* T = (k0 < H) ? T1 : T2;
            const int idx  = (k0 < H) ? idxA[xr] : idxB[xr];
            const int kk   = (k0 & (H - 1)) + xkv;
            float4 v = *(const float4*)(T + (size_t)idx * H + kk);
            Xs[(xkv + 0) * XP + xr] = v.x;
            Xs[(xkv + 1) * XP + xr] = v.y;
            Xs[(xkv + 2) * XP + xr] = v.z;
            Xs[(xkv + 3) * XP + xr] = v.w;
        }
        {   // W1 k-slice: row c = tid, stored transposed Ws[k][c]
            const float4* src = (const float4*)(W1 + (size_t)tid * H2 + k0);
            float4 w4[4];
#pragma unroll
            for (int q = 0; q < 4; q++) w4[q] = src[q];
#pragma unroll
            for (int q = 0; q < 4; q++) {
                Ws[(q * 4 + 0) * H + tid] = w4[q].x;
                Ws[(q * 4 + 1) * H + tid] = w4[q].y;
                Ws[(q * 4 + 2) * H + tid] = w4[q].z;
                Ws[(q * 4 + 3) * H + tid] = w4[q].w;
            }
        }
        __syncthreads();
#pragma unroll
        for (int k = 0; k < KT; k++) {
            float xv[8];
#pragma unroll
            for (int i = 0; i < 8; i++) xv[i] = Xs[k * XP + r0 + i];   // warp broadcast
            float4 wa = *(const float4*)(Ws + k * H + c0);
            float4 wb = *(const float4*)(Ws + k * H + c0 + 4);
            float wv[8] = {wa.x, wa.y, wa.z, wa.w, wb.x, wb.y, wb.z, wb.w};
#pragma unroll
            for (int i = 0; i < 8; i++)
#pragma unroll
                for (int j = 0; j < 8; j++)
                    acc[i][j] = fmaf(xv[i], wv[j], acc[i][j]);
        }
        __syncthreads();
    }

    // bias + relu -> Hs[r][c]
    {
        float4 ba = *(const float4*)(b1 + c0);
        float4 bb = *(const float4*)(b1 + c0 + 4);
        float bv[8] = {ba.x, ba.y, ba.z, ba.w, bb.x, bb.y, bb.z, bb.w};
#pragma unroll
        for (int i = 0; i < 8; i++) {
            float4 h0, h1v;
            h0.x = fmaxf(acc[i][0] + bv[0], 0.f);
            h0.y = fmaxf(acc[i][1] + bv[1], 0.f);
            h0.z = fmaxf(acc[i][2] + bv[2], 0.f);
            h0.w = fmaxf(acc[i][3] + bv[3], 0.f);
            h1v.x = fmaxf(acc[i][4] + bv[4], 0.f);
            h1v.y = fmaxf(acc[i][5] + bv[5], 0.f);
            h1v.z = fmaxf(acc[i][6] + bv[6], 0.f);
            h1v.w = fmaxf(acc[i][7] + bv[7], 0.f);
            *(float4*)(Hs + (r0 + i) * HP + c0)     = h0;
            *(float4*)(Hs + (r0 + i) * HP + c0 + 4) = h1v;
        }
    }
    __syncthreads();

    // ---- GEMM2: h[64x256] @ W2^T -> keys[64x256] ----
#pragma unroll
    for (int i = 0; i < 8; i++)
#pragma unroll
        for (int j = 0; j < 8; j++) acc[i][j] = 0.f;

    for (int kt = 0; kt < H / KT; kt++) {
        const int k0 = kt * KT;
        {
            const float4* src = (const float4*)(W2 + (size_t)tid * H + k0);
            float4 w4[4];
#pragma unroll
            for (int q = 0; q < 4; q++) w4[q] = src[q];
#pragma unroll
            for (int q = 0; q < 4; q++) {
                Ws[(q * 4 + 0) * H + tid] = w4[q].x;
                Ws[(q * 4 + 1) * H + tid] = w4[q].y;
                Ws[(q * 4 + 2) * H + tid] = w4[q].z;
                Ws[(q * 4 + 3) * H + tid] = w4[q].w;
            }
        }
        __syncthreads();
#pragma unroll
        for (int k = 0; k < KT; k++) {
            float xv[8];
#pragma unroll
            for (int i = 0; i < 8; i++) xv[i] = Hs[(r0 + i) * HP + k0 + k];  // broadcast
            float4 wa = *(const float4*)(Ws + k * H + c0);
            float4 wb = *(const float4*)(Ws + k * H + c0 + 4);
            float wv[8] = {wa.x, wa.y, wa.z, wa.w, wb.x, wb.y, wb.z, wb.w};
#pragma unroll
            for (int i = 0; i < 8; i++)
#pragma unroll
                for (int j = 0; j < 8; j++)
                    acc[i][j] = fmaf(xv[i], wv[j], acc[i][j]);
        }
        __syncthreads();
    }

    // keys = acc + b2 ; write to gmem scratch
    {
        float4 ba = *(const float4*)(b2 + c0);
        float4 bb = *(const float4*)(b2 + c0 + 4);
        float bv[8] = {ba.x, ba.y, ba.z, ba.w, bb.x, bb.y, bb.z, bb.w};
#pragma unroll
        for (int i = 0; i < 8; i++)
#pragma unroll
            for (int j = 0; j < 8; j++) acc[i][j] += bv[j];
#pragma unroll
        for (int i = 0; i < 8; i++) {
            float4 o0 = make_float4(acc[i][0], acc[i][1], acc[i][2], acc[i][3]);
            float4 o1 = make_float4(acc[i][4], acc[i][5], acc[i][6], acc[i][7]);
            size_t go = (size_t)(rowBase + r0 + i) * H + c0;
            *(float4*)(g_keys + go)     = o0;
            *(float4*)(g_keys + go + 4) = o1;
        }
    }
    __syncthreads();   // h dead; reuse Hs for keys
#pragma unroll
    for (int i = 0; i < 8; i++) {
        *(float4*)(Hs + (r0 + i) * HP + c0)     = make_float4(acc[i][0], acc[i][1], acc[i][2], acc[i][3]);
        *(float4*)(Hs + (r0 + i) * HP + c0 + 4) = make_float4(acc[i][4], acc[i][5], acc[i][6], acc[i][7]);
    }
    __syncthreads();

    // scores: thread = (row, head)
    {
        const int row = tid >> 2, h = tid & 3;
        float d = 0.f;
#pragma unroll 8
        for (int c = 0; c < H; c++) d = fmaf(Hs[row * HP + c], kqs[h * H + c], d);
        sc[tid] = (d + g_cK[h]) * 0.125f;   // 1/sqrt(64)
    }
    __syncthreads();
    if (tid < 4) {
        float m = -CUDART_INF_F;
        for (int r = 0; r < BR; r++) m = fmaxf(m, sc[r * 4 + tid]);
        mh[tid] = m;
    }
    __syncthreads();
    esh[tid] = expf(sc[tid] - mh[tid & 3]);
    __syncthreads();
    if (tid < 4) {
        float s = 0.f;
        for (int r = 0; r < BR; r++) s += esh[r * 4 + tid];
        g_ps[tid * NBLK_C + blk] = s;
        g_pm[tid * NBLK_C + blk] = mh[tid];
    }
    // weighted-keys accumulator: thread = column
#pragma unroll
    for (int h = 0; h < 4; h++) {
        float a = 0.f;
#pragma unroll 8
        for (int r = 0; r < BR; r++) a = fmaf(esh[r * 4 + h], Hs[r * HP + tid], a);
        g_pacc[((size_t)h * NBLK_C + blk) * H + tid] = a;
    }
}

// ---------------- kernel D1: combine 4096 softmax partials -> 64 ----------------
__global__ void kD1() {
    __shared__ float M[4];
    __shared__ float ew[BR * 4];
    const int tid = threadIdx.x, b = blockIdx.x;   // 64 blocks

    if (tid < 4) {
        float m = -CUDART_INF_F;
        for (int j = 0; j < 64; j++) m = fmaxf(m, g_pm[tid * NBLK_C + b + j * 64]);
        M[tid] = m;
    }
    __syncthreads();
    {
        const int j = tid >> 2, h = tid & 3;
        ew[tid] = expf(g_pm[h * NBLK_C + b + j * 64] - M[h]);
    }
    __syncthreads();
    if (tid < 4) {
        float s = 0.f;
        for (int j = 0; j < 64; j++) s += ew[j * 4 + tid] * g_ps[tid * NBLK_C + b + j * 64];
        g_s2[tid * 64 + b] = s;
        g_m2[tid * 64 + b] = M[tid];
    }
#pragma unroll
    for (int h = 0; h < 4; h++) {
        float a = 0.f;
        for (int j = 0; j < 64; j++)
            a = fmaf(ew[j * 4 + h], g_pacc[((size_t)h * NBLK_C + b + j * 64) * H + tid], a);
        g_acc2[(h * 64 + b) * H + tid] = a;
    }
}

// ---------------- kernel D2: final combine -> ctx -> attn_out ----------------
__global__ void kD2(const float* __restrict__ Wv, const float* __restrict__ bv,
                    const float* __restrict__ Wo, const float* __restrict__ bo) {
    __shared__ float M[4], S[4];
    __shared__ float ew[64 * 4];
    __shared__ float ACC[4 * H];
    __shared__ float ctx[H];
    const int tid = threadIdx.x;

    if (tid < 4) {
        float m = -CUDART_INF_F;
        for (int j = 0; j < 64; j++) m = fmaxf(m, g_m2[tid * 64 + j]);
        M[tid] = m;
    }
    __syncthreads();
    {
        const int j = tid >> 2, h = tid & 3;
        ew[tid] = expf(g_m2[h * 64 + j] - M[h]);
    }
    __syncthreads();
    if (tid < 4) {
        float s = 0.f;
        for (int j = 0; j < 64; j++) s += ew[j * 4 + tid] * g_s2[tid * 64 + j];
        S[tid] = s;
    }
    __syncthreads();
#pragma unroll
    for (int h = 0; h < 4; h++) {
        float a = 0.f;
        for (int j = 0; j < 64; j++)
            a = fmaf(ew[j * 4 + h], g_acc2[(h * 64 + j) * H + tid], a);
        ACC[h * H + tid] = a / S[h];
    }
    __syncthreads();
    {
        const int h = tid >> 6;
        float a = bv[tid];
#pragma unroll 8
        for (int c = 0; c < H; c++) a = fmaf(Wv[(size_t)tid * H + c], ACC[h * H + c], a);
        ctx[tid] = a;
    }
    __syncthreads();
    {
        float a = bo[tid];
#pragma unroll 8
        for (int j = 0; j < H; j++) a = fmaf(Wo[(size_t)tid * H + j], ctx[j], a);
        g_attn_out[tid] = a;
    }
    if (tid == 0) g_lmax = 0u;   // reset before E1 (graph replay safe)
}

// ---------------- kernel E1: logits = keys @ attn_out, track global max ----------------
__global__ void kE1(float* __restrict__ logits) {
    __shared__ float wmax[8];
    const int tid = threadIdx.x, lane = tid & 31, warp = tid >> 5;
    float ao[8];
    {
        float4 a0 = *(const float4*)(g_attn_out + lane * 8);
        float4 a1 = *(const float4*)(g_attn_out + lane * 8 + 4);
        ao[0] = a0.x; ao[1] = a0.y; ao[2] = a0.z; ao[3] = a0.w;
        ao[4] = a1.x; ao[5] = a1.y; ao[6] = a1.z; ao[7] = a1.w;
    }
    const int gw = blockIdx.x * 8 + warp;   // 8192 warps total
    float mx = -CUDART_INF_F;
    for (int r = gw; r < ATOT; r += 8192) {
        const float* kp = g_keys + (size_t)r * H + lane * 8;
        float4 k0 = *(const float4*)(kp);
        float4 k1 = *(const float4*)(kp + 4);
        float p = k0.x * ao[0];
        p = fmaf(k0.y, ao[1], p); p = fmaf(k0.z, ao[2], p); p = fmaf(k0.w, ao[3], p);
        p = fmaf(k1.x, ao[4], p); p = fmaf(k1.y, ao[5], p);
        p = fmaf(k1.z, ao[6], p); p = fmaf(k1.w, ao[7], p);
#pragma unroll
        for (int off = 16; off > 0; off >>= 1)
            p += __shfl_xor_sync(0xffffffffu, p, off);
        if (lane == 0) logits[r] = p;
        mx = fmaxf(mx, p);
    }
    if (lane == 0) wmax[warp] = mx;
    __syncthreads();
    if (tid == 0) {
        float m = wmax[0];
#pragma unroll
        for (int w = 1; w < 8; w++) m = fmaxf(m, wmax[w]);
        atomicMax(&g_lmax, fkey(m));
    }
}

// ---------------- kernel E2: partial sums of exp(logit - gmax) ----------------
__global__ void kE2(const float* __restrict__ logits) {
    __shared__ float red[256];
    const int tid = threadIdx.x;
    const float gm = funkey(g_lmax);
    float s = 0.f;
    for (int i = blockIdx.x * 256 + tid; i < ATOT; i += 256 * 256)
        s += expf(logits[i] - gm);
    red[tid] = s;
    __syncthreads();
    for (int o = 128; o > 0; o >>= 1) {
        if (tid < o) red[tid] += red[tid + o];
        __syncthreads();
    }
    if (tid == 0) g_lpart[blockIdx.x] = red[0];
}

// ---------------- kernel E4: finish sum (redundant per block) + probs ----------------
__global__ void kE4(const float* __restrict__ logits, float* __restrict__ probs) {
    __shared__ float red[256];
    const int tid = threadIdx.x;
    red[tid] = g_lpart[tid];
    __syncthreads();
    for (int o = 128; o > 0; o >>= 1) {
        if (tid < o) red[tid] += red[tid + o];
        __syncthreads();
    }
    const float gm  = funkey(g_lmax);
    const float inv = 1.0f / red[0];
    for (int i = blockIdx.x * 256 + tid; i < ATOT; i += 1024 * 256)
        probs[i] = expf(logits[i] - gm) * inv;
}

// ---------------- launch ----------------
extern "C" void kernel_launch(void* const* d_in, const int* in_sizes, int n_in,
                              void* d_out, int out_size) {
    const float* qubit_emb = (const float*)d_in[0];
    const float* qpu_emb   = (const float*)d_in[1];
    const float* gate_emb  = (const float*)d_in[2];
    const float* all_emb   = (const float*)d_in[3];
    const float* time_tab  = (const float*)d_in[4];
    const float* mW1 = (const float*)d_in[5];
    const float* mb1 = (const float*)d_in[6];
    const float* mW2 = (const float*)d_in[7];
    const float* mb2 = (const float*)d_in[8];
    const float* sW1 = (const float*)d_in[9];
    const float* sb1 = (const float*)d_in[10];
    const float* sW2 = (const float*)d_in[11];
    const float* sb2 = (const float*)d_in[12];
    const float* qgW1 = (const float*)d_in[13];
    const float* qgb1 = (const float*)d_in[14];
    const float* qgW2 = (const float*)d_in[15];
    const float* qgb2 = (const float*)d_in[16];
    const float* Wq = (const float*)d_in[17];
    const float* bq = (const float*)d_in[18];
    const float* Wk = (const float*)d_in[19];
    const float* bk = (const float*)d_in[20];
    const float* Wv = (const float*)d_in[21];
    const float* bv = (const float*)d_in[22];
    const float* Wo = (const float*)d_in[23];
    const float* bo = (const float*)d_in[24];
    const int* map_qubit  = (const int*)d_in[25];
    const int* map_qpu    = (const int*)d_in[26];
    const int* sched_gate = (const int*)d_in[27];
    const int* sched_time = (const int*)d_in[28];

    float* out    = (float*)d_out;
    float* probs  = out;
    float* logits = out + ATOT;

    const int SMEM_C = (KT * H + KT * XP + BR * HP + 4 * H + BR * 4 + BR * 4 + 4) * 4
                       + BR * 2 * 4;   // ~93.8 KB
    cudaFuncSetAttribute(kC, cudaFuncAttributeMaxDynamicSharedMemorySize, SMEM_C);

    kA<<<256, 256>>>(all_emb);
    kB<<<1, 256>>>(qgW1, qgb1, qgW2, qgb2, Wq, bq, Wk, bk);
    kC<<<NBLK_C, 256, SMEM_C>>>(qubit_emb, qpu_emb, gate_emb, time_tab,
                                mW1, mb1, mW2, mb2, sW1, sb1, sW2, sb2,
                                map_qubit, map_qpu, sched_gate, sched_time);
    kD1<<<64, 256>>>();
    kD2<<<1, 256>>>(Wv, bv, Wo, bo);
    kE1<<<1024, 256>>>(logits);
    kE2<<<256, 256>>>(logits);
    kE4<<<1024, 256>>>(logits, probs);
}

// round 3
// speedup vs baseline: 1.0594x; 1.0594x over previous
#include <cuda_runtime.h>
#include <math.h>
#include <math_constants.h>

#define H    256
#define H2   512
#define NMAP 131072
#define NSCH 131072
#define ATOT (NMAP + NSCH)
#define BR   64
#define NBLK_C (ATOT / BR)       // 4096
#define KT   16
#define XP   66                  // Xs row pad (conflict-free transposed stores)
#define HP   260                 // Hs row pad (mult of 4, spreads banks)

// packed fp32x2 helpers (sm_103a FFMA2 — only reachable via PTX)
#define FMA2(d, a, b) asm("fma.rn.f32x2 %0, %1, %2, %0;" : "+l"(d) : "l"(a), "l"(b))
#define SPLAT2(d, x)  asm("mov.b64 %0, {%1, %1};" : "=l"(d) : "r"(__float_as_uint(x)))
#define UNPK2(lo, hi, p) asm("mov.b64 {%0, %1}, %2;" : "=r"(lo), "=r"(hi) : "l"(p))

// ---------------- device scratch (allowed: __device__ globals) ----------------
static __device__ __align__(16) float g_keys[(size_t)ATOT * H];        // 268 MB
static __device__ __align__(16) float g_red[256 * H];
static __device__ __align__(16) float g_kq[4 * H];
static __device__ float g_cK[4];
static __device__ float g_pm[4 * NBLK_C];
static __device__ float g_ps[4 * NBLK_C];
static __device__ __align__(16) float g_pacc[(size_t)4 * NBLK_C * H];  // 16.8 MB
static __device__ float g_m2[4 * 64];
static __device__ float g_s2[4 * 64];
static __device__ __align__(16) float g_acc2[4 * 64 * H];
static __device__ __align__(16) float g_attn_out[H];
static __device__ unsigned int g_lmax;
static __device__ float g_lpart[256];

// ordered-int encoding for exact (order-independent) float atomicMax
__device__ __forceinline__ unsigned int fkey(float f) {
    unsigned int b = __float_as_uint(f);
    return (b & 0x80000000u) ? ~b : (b | 0x80000000u);
}
__device__ __forceinline__ float funkey(unsigned int k) {
    unsigned int b = (k & 0x80000000u) ? (k & 0x7fffffffu) : ~k;
    return __uint_as_float(b);
}

// ---------------- kernel A: column partial sums of all_embeddings ----------------
__global__ void kA(const float* __restrict__ all_emb) {
    const int c = threadIdx.x;          // 256 threads = 256 cols
    const int b = blockIdx.x;           // 256 blocks, 512 rows each
    const float* p = all_emb + (size_t)b * 512 * H + c;
    float s = 0.f;
#pragma unroll 8
    for (int r = 0; r < 512; r++) s += p[(size_t)r * H];
    g_red[b * H + c] = s;
}

// ---------------- kernel B: g-mean finish, query MLP, q proj, kq/cK fold ----------------
__global__ void kB(const float* __restrict__ qgW1, const float* __restrict__ qgb1,
                   const float* __restrict__ qgW2, const float* __restrict__ qgb2,
                   const float* __restrict__ Wq,  const float* __restrict__ bq,
                   const float* __restrict__ Wk,  const float* __restrict__ bk) {
    __shared__ float xs[H], h1[H], q2[H], qv[H];
    const int t = threadIdx.x;

    float s = 0.f;
#pragma unroll 8
    for (int b = 0; b < 256; b++) s += g_red[b * H + t];
    xs[t] = s * (1.0f / 131072.0f);
    __syncthreads();

    float a = qgb1[t];
#pragma unroll 8
    for (int c = 0; c < H; c++) a = fmaf(qgW1[(size_t)t * H + c], xs[c], a);
    h1[t] = fmaxf(a, 0.f);
    __syncthreads();

    a = qgb2[t];
#pragma unroll 8
    for (int c = 0; c < H; c++) a = fmaf(qgW2[(size_t)t * H + c], h1[c], a);
    q2[t] = a;
    __syncthreads();

    a = bq[t];
#pragma unroll 8
    for (int c = 0; c < H; c++) a = fmaf(Wq[(size_t)t * H + c], q2[c], a);
    qv[t] = a;
    __syncthreads();

    // kq_h[c] = sum_d Wk[h*64+d][c] * qv[h*64+d]   (coalesced: thread t = col c)
#pragma unroll
    for (int h = 0; h < 4; h++) {
        float a2 = 0.f;
#pragma unroll 8
        for (int d = 0; d < 64; d++)
            a2 = fmaf(Wk[(size_t)(h * 64 + d) * H + t], qv[h * 64 + d], a2);
        g_kq[h * H + t] = a2;
    }
    if (t < 4) {
        float a2 = 0.f;
        for (int d = 0; d < 64; d++) a2 = fmaf(bk[t * 64 + d], qv[t * 64 + d], a2);
        g_cK[t] = a2;
    }
}

// ---------------- kernel C: fused gather + MLP + keys + scores + softmax partials ----------------
__global__ void __launch_bounds__(256, 2)
kC(const float* __restrict__ qubit_emb, const float* __restrict__ qpu_emb,
   const float* __restrict__ gate_emb,  const float* __restrict__ time_tab,
   const float* __restrict__ mW1, const float* __restrict__ mb1,
   const float* __restrict__ mW2, const float* __restrict__ mb2,
   const float* __restrict__ sW1, const float* __restrict__ sb1,
   const float* __restrict__ sW2, const float* __restrict__ sb2,
   const int* __restrict__ map_qubit, const int* __restrict__ map_qpu,
   const int* __restrict__ sched_gate, const int* __restrict__ sched_time) {
    extern __shared__ float sm[];
    float* Ws  = sm;                       // KT*H   = 4096 floats
    float* Xs  = Ws  + KT * H;             // KT*XP  = 1056
    float* Hs  = Xs  + KT * XP;            // BR*HP  = 16640
    float* kqs = Hs  + BR * HP;            // 4*H    = 1024
    float* sc  = kqs + 4 * H;              // BR*4
    float* esh = sc  + BR * 4;             // BR*4
    float* mh  = esh + BR * 4;             // 4
    int*   idxA = (int*)(mh + 4);          // BR
    int*   idxB = idxA + BR;               // BR

    const int tid = threadIdx.x;
    const int blk = blockIdx.x;
    const long rowBase = (long)blk * BR;
    const bool isMap = (rowBase < NMAP);

    const float* T1 = isMap ? qubit_emb : gate_emb;
    const float* T2 = isMap ? qpu_emb   : time_tab;
    const float* W1 = isMap ? mW1 : sW1;
    const float* b1 = isMap ? mb1 : sb1;
    const float* W2 = isMap ? mW2 : sW2;
    const float* b2 = isMap ? mb2 : sb2;

    if (tid < BR) {
        long ib = isMap ? (rowBase + tid) : (rowBase - NMAP + tid);
        idxA[tid] = isMap ? map_qubit[ib] : sched_gate[ib];
        idxB[tid] = isMap ? map_qpu[ib]   : sched_time[ib];
    }
    for (int i = tid; i < 4 * H; i += 256) kqs[i] = g_kq[i];
    __syncthreads();

    const int warp = tid >> 5, lane = tid & 31;
    const int r0 = warp * 8;   // 8 warps x 8 rows = 64
    const int c0 = lane * 8;   // 32 lanes x 8 cols = 256

    // packed accumulators: acc[i][jp] holds cols (c0+2jp, c0+2jp+1) for row r0+i
    unsigned long long acc[8][4];
#pragma unroll
    for (int i = 0; i < 8; i++)
#pragma unroll
        for (int j = 0; j < 4; j++) acc[i][j] = 0ull;

    const int xr  = tid >> 2;
    const int xkv = (tid & 3) * 4;

    // ---- GEMM1: X[64x512] @ W1^T -> h[64x256] ----
    for (int kt = 0; kt < H2 / KT; kt++) {
        const int k0 = kt * KT;
        {   // X k-slice (gather), stored transposed Xs[k][r]
            const float* T = (k0 < H) ? T1 : T2;
            const int idx  = (k0 < H) ? idxA[xr] : idxB[xr];
            const int kk   = (k0 & (H - 1)) + xkv;
            float4 v = *(const float4*)(T + (size_t)idx * H + kk);
            Xs[(xkv + 0) * XP + xr] = v.x;
            Xs[(xkv + 1) * XP + xr] = v.y;
            Xs[(xkv + 2) * XP + xr] = v.z;
            Xs[(xkv + 3) * XP + xr] = v.w;
        }
        {   // W1 k-slice: row c = tid, stored transposed Ws[k][c]
            const float4* src = (const float4*)(W1 + (size_t)tid * H2 + k0);
            float4 w4[4];
#pragma unroll
            for (int q = 0; q < 4; q++) w4[q] = src[q];
#pragma unroll
            for (int q = 0; q < 4; q++) {
                Ws[(q * 4 + 0) * H + tid] = w4[q].x;
                Ws[(q * 4 + 1) * H + tid] = w4[q].y;
                Ws[(q * 4 + 2) * H + tid] = w4[q].z;
                Ws[(q * 4 + 3) * H + tid] = w4[q].w;
            }
        }
        __syncthreads();
#pragma unroll
        for (int k = 0; k < KT; k++) {
            unsigned long long xx[8];
#pragma unroll
            for (int i = 0; i < 8; i++) {
                float x = Xs[k * XP + r0 + i];   // warp broadcast
                SPLAT2(xx[i], x);
            }
            const ulonglong2* wp = (const ulonglong2*)(Ws + k * H + c0);
            ulonglong2 wa = wp[0], wb = wp[1];   // 2x LDS.128 = 8 packed cols
            unsigned long long wv[4] = {wa.x, wa.y, wb.x, wb.y};
#pragma unroll
            for (int i = 0; i < 8; i++)
#pragma unroll
                for (int j = 0; j < 4; j++)
                    FMA2(acc[i][j], xx[i], wv[j]);
        }
        __syncthreads();
    }

    // bias + relu -> Hs[r][c]
    {
        float4 ba = *(const float4*)(b1 + c0);
        float4 bb = *(const float4*)(b1 + c0 + 4);
        float bv[8] = {ba.x, ba.y, ba.z, ba.w, bb.x, bb.y, bb.z, bb.w};
#pragma unroll
        for (int i = 0; i < 8; i++) {
            float f[8];
#pragma unroll
            for (int j = 0; j < 4; j++) {
                unsigned int lo, hi;
                UNPK2(lo, hi, acc[i][j]);
                f[2 * j]     = __uint_as_float(lo);
                f[2 * j + 1] = __uint_as_float(hi);
            }
            float4 h0, h1v;
            h0.x = fmaxf(f[0] + bv[0], 0.f);
            h0.y = fmaxf(f[1] + bv[1], 0.f);
            h0.z = fmaxf(f[2] + bv[2], 0.f);
            h0.w = fmaxf(f[3] + bv[3], 0.f);
            h1v.x = fmaxf(f[4] + bv[4], 0.f);
            h1v.y = fmaxf(f[5] + bv[5], 0.f);
            h1v.z = fmaxf(f[6] + bv[6], 0.f);
            h1v.w = fmaxf(f[7] + bv[7], 0.f);
            *(float4*)(Hs + (r0 + i) * HP + c0)     = h0;
            *(float4*)(Hs + (r0 + i) * HP + c0 + 4) = h1v;
        }
    }
    __syncthreads();

    // ---- GEMM2: h[64x256] @ W2^T -> keys[64x256] ----
#pragma unroll
    for (int i = 0; i < 8; i++)
#pragma unroll
        for (int j = 0; j < 4; j++) acc[i][j] = 0ull;

    for (int kt = 0; kt < H / KT; kt++) {
        const int k0 = kt * KT;
        {
            const float4* src = (const float4*)(W2 + (size_t)tid * H + k0);
            float4 w4[4];
#pragma unroll
            for (int q = 0; q < 4; q++) w4[q] = src[q];
#pragma unroll
            for (int q = 0; q < 4; q++) {
                Ws[(q * 4 + 0) * H + tid] = w4[q].x;
                Ws[(q * 4 + 1) * H + tid] = w4[q].y;
                Ws[(q * 4 + 2) * H + tid] = w4[q].z;
                Ws[(q * 4 + 3) * H + tid] = w4[q].w;
            }
        }
        __syncthreads();
#pragma unroll
        for (int k = 0; k < KT; k++) {
            unsigned long long xx[8];
#pragma unroll
            for (int i = 0; i < 8; i++) {
                float x = Hs[(r0 + i) * HP + k0 + k];  // broadcast
                SPLAT2(xx[i], x);
            }
            const ulonglong2* wp = (const ulonglong2*)(Ws + k * H + c0);
            ulonglong2 wa = wp[0], wb = wp[1];
            unsigned long long wv[4] = {wa.x, wa.y, wb.x, wb.y};
#pragma unroll
            for (int i = 0; i < 8; i++)
#pragma unroll
                for (int j = 0; j < 4; j++)
                    FMA2(acc[i][j], xx[i], wv[j]);
        }
        __syncthreads();
    }

    // keys = acc + b2 ; write to gmem scratch and to Hs (reuse)
    float keyf[8][8];
    {
        float4 ba = *(const float4*)(b2 + c0);
        float4 bb = *(const float4*)(b2 + c0 + 4);
        float bv[8] = {ba.x, ba.y, ba.z, ba.w, bb.x, bb.y, bb.z, bb.w};
#pragma unroll
        for (int i = 0; i < 8; i++) {
#pragma unroll
            for (int j = 0; j < 4; j++) {
                unsigned int lo, hi;
                UNPK2(lo, hi, acc[i][j]);
                keyf[i][2 * j]     = __uint_as_float(lo) + bv[2 * j];
                keyf[i][2 * j + 1] = __uint_as_float(hi) + bv[2 * j + 1];
            }
        }
#pragma unroll
        for (int i = 0; i < 8; i++) {
            float4 o0 = make_float4(keyf[i][0], keyf[i][1], keyf[i][2], keyf[i][3]);
            float4 o1 = make_float4(keyf[i][4], keyf[i][5], keyf[i][6], keyf[i][7]);
            size_t go = (size_t)(rowBase + r0 + i) * H + c0;
            *(float4*)(g_keys + go)     = o0;
            *(float4*)(g_keys + go + 4) = o1;
        }
    }
    __syncthreads();   // h dead; reuse Hs for keys
#pragma unroll
    for (int i = 0; i < 8; i++) {
        *(float4*)(Hs + (r0 + i) * HP + c0)     = make_float4(keyf[i][0], keyf[i][1], keyf[i][2], keyf[i][3]);
        *(float4*)(Hs + (r0 + i) * HP + c0 + 4) = make_float4(keyf[i][4], keyf[i][5], keyf[i][6], keyf[i][7]);
    }
    __syncthreads();

    // scores: thread = (row, head)
    {
        const int row = tid >> 2, h = tid & 3;
        float d = 0.f;
#pragma unroll 8
        for (int c = 0; c < H; c++) d = fmaf(Hs[row * HP + c], kqs[h * H + c], d);
        sc[tid] = (d + g_cK[h]) * 0.125f;   // 1/sqrt(64)
    }
    __syncthreads();
    if (tid < 4) {
        float m = -CUDART_INF_F;
        for (int r = 0; r < BR; r++) m = fmaxf(m, sc[r * 4 + tid]);
        mh[tid] = m;
    }
    __syncthreads();
    esh[tid] = expf(sc[tid] - mh[tid & 3]);
    __syncthreads();
    if (tid < 4) {
        float s = 0.f;
        for (int r = 0; r < BR; r++) s += esh[r * 4 + tid];
        g_ps[tid * NBLK_C + blk] = s;
        g_pm[tid * NBLK_C + blk] = mh[tid];
    }
    // weighted-keys accumulator: thread = column
#pragma unroll
    for (int h = 0; h < 4; h++) {
        float a = 0.f;
#pragma unroll 8
        for (int r = 0; r < BR; r++) a = fmaf(esh[r * 4 + h], Hs[r * HP + tid], a);
        g_pacc[((size_t)h * NBLK_C + blk) * H + tid] = a;
    }
}

// ---------------- kernel D1: combine 4096 softmax partials -> 64 ----------------
__global__ void kD1() {
    __shared__ float M[4];
    __shared__ float ew[BR * 4];
    const int tid = threadIdx.x, b = blockIdx.x;   // 64 blocks

    if (tid < 4) {
        float m = -CUDART_INF_F;
        for (int j = 0; j < 64; j++) m = fmaxf(m, g_pm[tid * NBLK_C + b + j * 64]);
        M[tid] = m;
    }
    __syncthreads();
    {
        const int j = tid >> 2, h = tid & 3;
        ew[tid] = expf(g_pm[h * NBLK_C + b + j * 64] - M[h]);
    }
    __syncthreads();
    if (tid < 4) {
        float s = 0.f;
        for (int j = 0; j < 64; j++) s += ew[j * 4 + tid] * g_ps[tid * NBLK_C + b + j * 64];
        g_s2[tid * 64 + b] = s;
        g_m2[tid * 64 + b] = M[tid];
    }
#pragma unroll
    for (int h = 0; h < 4; h++) {
        float a = 0.f;
        for (int j = 0; j < 64; j++)
            a = fmaf(ew[j * 4 + h], g_pacc[((size_t)h * NBLK_C + b + j * 64) * H + tid], a);
        g_acc2[(h * 64 + b) * H + tid] = a;
    }
}

// ---------------- kernel D2: final combine -> ctx -> attn_out ----------------
__global__ void kD2(const float* __restrict__ Wv, const float* __restrict__ bv,
                    const float* __restrict__ Wo, const float* __restrict__ bo) {
    __shared__ float M[4], S[4];
    __shared__ float ew[64 * 4];
    __shared__ float ACC[4 * H];
    __shared__ float ctx[H];
    const int tid = threadIdx.x;

    if (tid < 4) {
        float m = -CUDART_INF_F;
        for (int j = 0; j < 64; j++) m = fmaxf(m, g_m2[tid * 64 + j]);
        M[tid] = m;
    }
    __syncthreads();
    {
        const int j = tid >> 2, h = tid & 3;
        ew[tid] = expf(g_m2[h * 64 + j] - M[h]);
    }
    __syncthreads();
    if (tid < 4) {
        float s = 0.f;
        for (int j = 0; j < 64; j++) s += ew[j * 4 + tid] * g_s2[tid * 64 + j];
        S[tid] = s;
    }
    __syncthreads();
#pragma unroll
    for (int h = 0; h < 4; h++) {
        float a = 0.f;
        for (int j = 0; j < 64; j++)
            a = fmaf(ew[j * 4 + h], g_acc2[(h * 64 + j) * H + tid], a);
        ACC[h * H + tid] = a / S[h];
    }
    __syncthreads();
    {
        const int h = tid >> 6;
        float a = bv[tid];
#pragma unroll 8
        for (int c = 0; c < H; c++) a = fmaf(Wv[(size_t)tid * H + c], ACC[h * H + c], a);
        ctx[tid] = a;
    }
    __syncthreads();
    {
        float a = bo[tid];
#pragma unroll 8
        for (int j = 0; j < H; j++) a = fmaf(Wo[(size_t)tid * H + j], ctx[j], a);
        g_attn_out[tid] = a;
    }
    if (tid == 0) g_lmax = 0u;   // reset before E1 (graph replay safe)
}

// ---------------- kernel E1: logits = keys @ attn_out, track global max ----------------
__global__ void kE1(float* __restrict__ logits) {
    __shared__ float wmax[8];
    const int tid = threadIdx.x, lane = tid & 31, warp = tid >> 5;
    float ao[8];
    {
        float4 a0 = *(const float4*)(g_attn_out + lane * 8);
        float4 a1 = *(const float4*)(g_attn_out + lane * 8 + 4);
        ao[0] = a0.x; ao[1] = a0.y; ao[2] = a0.z; ao[3] = a0.w;
        ao[4] = a1.x; ao[5] = a1.y; ao[6] = a1.z; ao[7] = a1.w;
    }
    const int gw = blockIdx.x * 8 + warp;   // 8192 warps total
    float mx = -CUDART_INF_F;
    for (int r = gw; r < ATOT; r += 8192) {
        const float* kp = g_keys + (size_t)r * H + lane * 8;
        float4 k0 = *(const float4*)(kp);
        float4 k1 = *(const float4*)(kp + 4);
        float p = k0.x * ao[0];
        p = fmaf(k0.y, ao[1], p); p = fmaf(k0.z, ao[2], p); p = fmaf(k0.w, ao[3], p);
        p = fmaf(k1.x, ao[4], p); p = fmaf(k1.y, ao[5], p);
        p = fmaf(k1.z, ao[6], p); p = fmaf(k1.w, ao[7], p);
#pragma unroll
        for (int off = 16; off > 0; off >>= 1)
            p += __shfl_xor_sync(0xffffffffu, p, off);
        if (lane == 0) logits[r] = p;
        mx = fmaxf(mx, p);
    }
    if (lane == 0) wmax[warp] = mx;
    __syncthreads();
    if (tid == 0) {
        float m = wmax[0];
#pragma unroll
        for (int w = 1; w < 8; w++) m = fmaxf(m, wmax[w]);
        atomicMax(&g_lmax, fkey(m));
    }
}

// ---------------- kernel E2: partial sums of exp(logit - gmax) ----------------
__global__ void kE2(const float* __restrict__ logits) {
    __shared__ float red[256];
    const int tid = threadIdx.x;
    const float gm = funkey(g_lmax);
    float s = 0.f;
    for (int i = blockIdx.x * 256 + tid; i < ATOT; i += 256 * 256)
        s += expf(logits[i] - gm);
    red[tid] = s;
    __syncthreads();
    for (int o = 128; o > 0; o >>= 1) {
        if (tid < o) red[tid] += red[tid + o];
        __syncthreads();
    }
    if (tid == 0) g_lpart[blockIdx.x] = red[0];
}

// ---------------- kernel E4: finish sum (redundant per block) + probs ----------------
__global__ void kE4(const float* __restrict__ logits, float* __restrict__ probs) {
    __shared__ float red[256];
    const int tid = threadIdx.x;
    red[tid] = g_lpart[tid];
    __syncthreads();
    for (int o = 128; o > 0; o >>= 1) {
        if (tid < o) red[tid] += red[tid + o];
        __syncthreads();
    }
    const float gm  = funkey(g_lmax);
    const float inv = 1.0f / red[0];
    for (int i = blockIdx.x * 256 + tid; i < ATOT; i += 1024 * 256)
        probs[i] = expf(logits[i] - gm) * inv;
}

// ---------------- launch ----------------
extern "C" void kernel_launch(void* const* d_in, const int* in_sizes, int n_in,
                              void* d_out, int out_size) {
    const float* qubit_emb = (const float*)d_in[0];
    const float* qpu_emb   = (const float*)d_in[1];
    const float* gate_emb  = (const float*)d_in[2];
    const float* all_emb   = (const float*)d_in[3];
    const float* time_tab  = (const float*)d_in[4];
    const float* mW1 = (const float*)d_in[5];
    const float* mb1 = (const float*)d_in[6];
    const float* mW2 = (const float*)d_in[7];
    const float* mb2 = (const float*)d_in[8];
    const float* sW1 = (const float*)d_in[9];
    const float* sb1 = (const float*)d_in[10];
    const float* sW2 = (const float*)d_in[11];
    const float* sb2 = (const float*)d_in[12];
    const float* qgW1 = (const float*)d_in[13];
    const float* qgb1 = (const float*)d_in[14];
    const float* qgW2 = (const float*)d_in[15];
    const float* qgb2 = (const float*)d_in[16];
    const float* Wq = (const float*)d_in[17];
    const float* bq = (const float*)d_in[18];
    const float* Wk = (const float*)d_in[19];
    const float* bk = (const float*)d_in[20];
    const float* Wv = (const float*)d_in[21];
    const float* bv = (const float*)d_in[22];
    const float* Wo = (const float*)d_in[23];
    const float* bo = (const float*)d_in[24];
    const int* map_qubit  = (const int*)d_in[25];
    const int* map_qpu    = (const int*)d_in[26];
    const int* sched_gate = (const int*)d_in[27];
    const int* sched_time = (const int*)d_in[28];

    float* out    = (float*)d_out;
    float* probs  = out;
    float* logits = out + ATOT;

    const int SMEM_C = (KT * H + KT * XP + BR * HP + 4 * H + BR * 4 + BR * 4 + 4) * 4
                       + BR * 2 * 4;   // ~93.8 KB
    cudaFuncSetAttribute(kC, cudaFuncAttributeMaxDynamicSharedMemorySize, SMEM_C);

    kA<<<256, 256>>>(all_emb);
    kB<<<1, 256>>>(qgW1, qgb1, qgW2, qgb2, Wq, bq, Wk, bk);
    kC<<<NBLK_C, 256, SMEM_C>>>(qubit_emb, qpu_emb, gate_emb, time_tab,
                                mW1, mb1, mW2, mb2, sW1, sb1, sW2, sb2,
                                map_qubit, map_qpu, sched_gate, sched_time);
    kD1<<<64, 256>>>();
    kD2<<<1, 256>>>(Wv, bv, Wo, bo);
    kE1<<<1024, 256>>>(logits);
    kE2<<<256, 256>>>(logits);
    kE4<<<1024, 256>>>(logits, probs);
}